// round 1
// baseline (speedup 1.0000x reference)
#include <cuda_runtime.h>
#include <cuda_bf16.h>
#include <stdint.h>

// Scatter-mean: out = [ids(N) ; agg(N,D)] (fp32), or agg-only if out_size % (D+1) != 0.
// Pipeline: detect id dtype -> init (zero sums/counts, write iota) -> scatter (red.v4) -> normalize.

#define MAX_NODES (1 << 20)

__device__ int   g_is64;
__device__ float g_counts[MAX_NODES];

__device__ __forceinline__ void red_add_v4(float* addr, float4 v) {
    asm volatile("red.global.add.v4.f32 [%0], {%1, %2, %3, %4};"
                 :: "l"(addr), "f"(v.x), "f"(v.y), "f"(v.z), "f"(v.w) : "memory");
}
__device__ __forceinline__ void red_add_f32(float* addr, float v) {
    asm volatile("red.global.add.f32 [%0], %1;"
                 :: "l"(addr), "f"(v) : "memory");
}

// Detect whether node_ids buffer is int64 (all high 32-bit words zero) or int32.
__global__ void detect_kernel(const unsigned int* __restrict__ words, int M) {
    __shared__ int any_nonzero;
    if (threadIdx.x == 0) any_nonzero = 0;
    __syncthreads();
    int n = M < 4096 ? M : 4096;
    for (int i = threadIdx.x; i < n; i += blockDim.x) {
        // Under an int64 interpretation, words[2i+1] is the high word (== 0 for small ids).
        if (words[2 * i + 1] != 0u) any_nonzero = 1;
    }
    __syncthreads();
    if (threadIdx.x == 0) g_is64 = any_nonzero ? 0 : 1;
}

// Zero the sums region + counts; write the iota ids output.
__global__ void init_kernel(float* __restrict__ sums, float* __restrict__ ids_out,
                            int N, int D, int has_ids) {
    long long total4 = (long long)N * D / 4;
    float4 z = make_float4(0.f, 0.f, 0.f, 0.f);
    float4* s4 = (float4*)sums;
    for (long long i = blockIdx.x * (long long)blockDim.x + threadIdx.x;
         i < total4; i += (long long)gridDim.x * blockDim.x) {
        s4[i] = z;
    }
    for (long long i = blockIdx.x * (long long)blockDim.x + threadIdx.x;
         i < N; i += (long long)gridDim.x * blockDim.x) {
        g_counts[i] = 0.f;
        if (has_ids) ids_out[i] = (float)i;
    }
}

// One warp per message: 32 lanes each carry a float4 (D=128) and issue red.global.add.v4.
__global__ void scatter_kernel(const void* __restrict__ ids,
                               const float* __restrict__ msgs,
                               float* __restrict__ sums,
                               int M, int D) {
    int gwarp = (blockIdx.x * blockDim.x + threadIdx.x) >> 5;
    int lane  = threadIdx.x & 31;
    if (gwarp >= M) return;

    int id;
    if (g_is64) id = (int)((const long long*)ids)[gwarp];
    else        id = ((const int*)ids)[gwarp];

    const float4* row = (const float4*)(msgs + (size_t)gwarp * D);
    float* dst_row = sums + (size_t)id * D;

    // D == 128 in this problem: one float4 per lane. Loop kept for generality.
    #pragma unroll 1
    for (int c4 = lane; c4 * 4 < D; c4 += 32) {
        float4 v = row[c4];
        red_add_v4(dst_row + c4 * 4, v);
    }
    if (lane == 0) red_add_f32(&g_counts[id], 1.0f);
}

// In-place normalize: agg[row] = sums[row] / max(count[row], 1)
__global__ void normalize_kernel(float* __restrict__ sums, int N, int D) {
    long long total4 = (long long)N * D / 4;
    int d4 = D / 4;
    float4* s4 = (float4*)sums;
    for (long long i = blockIdx.x * (long long)blockDim.x + threadIdx.x;
         i < total4; i += (long long)gridDim.x * blockDim.x) {
        int row = (int)(i / d4);
        float c = g_counts[row];
        float inv = 1.0f / fmaxf(c, 1.0f);
        float4 v = s4[i];
        v.x *= inv; v.y *= inv; v.z *= inv; v.w *= inv;
        s4[i] = v;
    }
}

extern "C" void kernel_launch(void* const* d_in, const int* in_sizes, int n_in,
                              void* d_out, int out_size) {
    const void*  ids  = d_in[0];
    const float* msgs = (const float*)d_in[1];

    int M = in_sizes[0];
    int D = in_sizes[1] / M;   // 128

    // Output layout: [ids(N) ; agg(N*D)] if divisible by D+1, else agg-only.
    int N, has_ids;
    if (out_size % (D + 1) == 0 && (out_size / (D + 1)) * (D + 1) == out_size) {
        N = out_size / (D + 1);
        has_ids = 1;
    } else {
        N = out_size / D;
        has_ids = 0;
    }

    float* out     = (float*)d_out;
    float* ids_out = out;
    float* sums    = has_ids ? (out + N) : out;

    detect_kernel<<<1, 256>>>((const unsigned int*)ids, M);

    {
        long long total4 = (long long)N * D / 4;
        int blocks = (int)((total4 + 255) / 256);
        if (blocks > 4096) blocks = 4096;
        init_kernel<<<blocks, 256>>>(sums, ids_out, N, D, has_ids);
    }

    {
        long long threads = (long long)M * 32;
        int blocks = (int)((threads + 255) / 256);
        scatter_kernel<<<blocks, 256>>>(ids, msgs, sums, M, D);
    }

    {
        long long total4 = (long long)N * D / 4;
        int blocks = (int)((total4 + 255) / 256);
        if (blocks > 4096) blocks = 4096;
        normalize_kernel<<<blocks, 256>>>(sums, N, D);
    }
}